// round 3
// baseline (speedup 1.0000x reference)
#include <cuda_runtime.h>
#include <math.h>

// Problem constants
#define DIMC 768
#define NTOK 4096      // 4 batches * 1024 tokens per stream
#define QKVN 2304      // 3*DIM
#define HEADS 12
#define NBH 48         // 4*12
#define SEQ 2048       // concat seq
#define HD 64

// ---------------- scratch (device globals; no allocations allowed) ----------
__device__ float g_qkv0[NTOK * QKVN];
__device__ float g_qkv1[NTOK * QKVN];
__device__ float g_q[NBH * SEQ * HD];
__device__ float g_k[NBH * SEQ * HD];
__device__ float g_v[NBH * SEQ * HD];
__device__ float g_ao0[NTOK * DIMC];
__device__ float g_ao1[NTOK * DIMC];

// ---------------- SGEMM: C[M,N] = A[M,K] @ B[N,K]^T + bias[N] ---------------
// 128x128 tile, BK=8, 256 threads, 8x8 microtile, double-buffered smem.
__global__ __launch_bounds__(256, 2)
void sgemm_nt_bias(const float* __restrict__ A, const float* __restrict__ B,
                   const float* __restrict__ bias, float* __restrict__ C,
                   int M, int N, int K)
{
    __shared__ float As[2][8][128];
    __shared__ float Bs[2][8][128];

    const int tid = threadIdx.x;
    const int bm = blockIdx.y * 128;
    const int bn = blockIdx.x * 128;
    const int lr = tid >> 1;          // 0..127
    const int lk = (tid & 1) << 2;    // 0 or 4
    const float* Ap = A + (size_t)(bm + lr) * K + lk;
    const float* Bp = B + (size_t)(bn + lr) * K + lk;
    const int tx = tid & 15;
    const int ty = tid >> 4;

    float acc[8][8];
#pragma unroll
    for (int i = 0; i < 8; i++)
#pragma unroll
        for (int j = 0; j < 8; j++) acc[i][j] = 0.f;

    // prologue: stage k0=0 into buffer 0
    {
        float4 av = *(const float4*)(Ap + 0);
        float4 bv = *(const float4*)(Bp + 0);
        As[0][lk + 0][lr] = av.x; As[0][lk + 1][lr] = av.y;
        As[0][lk + 2][lr] = av.z; As[0][lk + 3][lr] = av.w;
        Bs[0][lk + 0][lr] = bv.x; Bs[0][lk + 1][lr] = bv.y;
        Bs[0][lk + 2][lr] = bv.z; Bs[0][lk + 3][lr] = bv.w;
    }
    __syncthreads();

    int buf = 0;
    for (int k0 = 0; k0 < K; k0 += 8) {
        // issue next tile's global loads early (hidden behind the FMA block)
        float4 av, bv;
        const bool more = (k0 + 8 < K);
        if (more) {
            av = *(const float4*)(Ap + k0 + 8);
            bv = *(const float4*)(Bp + k0 + 8);
        }

#pragma unroll
        for (int kk = 0; kk < 8; kk++) {
            float4 a0 = *(const float4*)&As[buf][kk][ty * 4];
            float4 a1 = *(const float4*)&As[buf][kk][ty * 4 + 64];
            float4 b0 = *(const float4*)&Bs[buf][kk][tx * 4];
            float4 b1 = *(const float4*)&Bs[buf][kk][tx * 4 + 64];
            float ar[8] = {a0.x, a0.y, a0.z, a0.w, a1.x, a1.y, a1.z, a1.w};
            float br[8] = {b0.x, b0.y, b0.z, b0.w, b1.x, b1.y, b1.z, b1.w};
#pragma unroll
            for (int i = 0; i < 8; i++)
#pragma unroll
                for (int j = 0; j < 8; j++)
                    acc[i][j] += ar[i] * br[j];
        }

        if (more) {
            int nb = buf ^ 1;
            As[nb][lk + 0][lr] = av.x; As[nb][lk + 1][lr] = av.y;
            As[nb][lk + 2][lr] = av.z; As[nb][lk + 3][lr] = av.w;
            Bs[nb][lk + 0][lr] = bv.x; Bs[nb][lk + 1][lr] = bv.y;
            Bs[nb][lk + 2][lr] = bv.z; Bs[nb][lk + 3][lr] = bv.w;
            __syncthreads();
            buf = nb;
        }
    }

#pragma unroll
    for (int i = 0; i < 8; i++) {
        int r = bm + ((i < 4) ? (ty * 4 + i) : (64 + ty * 4 + (i - 4)));
#pragma unroll
        for (int jg = 0; jg < 2; jg++) {
            int c = bn + tx * 4 + jg * 64;
            float4 o;
            o.x = acc[i][jg * 4 + 0] + bias[c + 0];
            o.y = acc[i][jg * 4 + 1] + bias[c + 1];
            o.z = acc[i][jg * 4 + 2] + bias[c + 2];
            o.w = acc[i][jg * 4 + 3] + bias[c + 3];
            *(float4*)&C[(size_t)r * N + c] = o;
        }
    }
}

// ---------------- LayerNorm(q,k per head) + split/rearrange -----------------
__device__ __forceinline__ float warp_sum32(float v) {
#pragma unroll
    for (int o = 16; o > 0; o >>= 1) v += __shfl_xor_sync(0xffffffffu, v, o);
    return v;
}

// one warp per (token, head). Applies LN to q,k (with gamma/beta), copies v,
// folds the 1/sqrt(HD)=0.125 attention scale into q.
__global__ void ln_split(const float* __restrict__ qkv,
                         const float* __restrict__ gq, const float* __restrict__ bq,
                         const float* __restrict__ gk, const float* __restrict__ bk,
                         int strm)
{
    const int row = blockIdx.x;                  // 0..NTOK*HEADS-1
    const int t = row / HEADS, h = row % HEADS;
    const int lane = threadIdx.x;
    const float* p = qkv + (size_t)t * QKVN + h * HD;
    const int b = t >> 10, n = t & 1023;
    const size_t dst = ((size_t)(b * HEADS + h) * SEQ + strm * 1024 + n) * HD;

    // q with LN (+0.125 scale)
    float q0 = p[lane], q1 = p[lane + 32];
    float mu = warp_sum32(q0 + q1) * (1.f / 64.f);
    float var = warp_sum32(q0 * q0 + q1 * q1) * (1.f / 64.f) - mu * mu;
    float inv = rsqrtf(var + 1e-5f);
    g_q[dst + lane]      = ((q0 - mu) * inv * gq[lane]      + bq[lane])      * 0.125f;
    g_q[dst + lane + 32] = ((q1 - mu) * inv * gq[lane + 32] + bq[lane + 32]) * 0.125f;

    // k with LN
    float k0 = p[DIMC + lane], k1 = p[DIMC + lane + 32];
    mu = warp_sum32(k0 + k1) * (1.f / 64.f);
    var = warp_sum32(k0 * k0 + k1 * k1) * (1.f / 64.f) - mu * mu;
    inv = rsqrtf(var + 1e-5f);
    g_k[dst + lane]      = (k0 - mu) * inv * gk[lane]      + bk[lane];
    g_k[dst + lane + 32] = (k1 - mu) * inv * gk[lane + 32] + bk[lane + 32];

    // v copy
    g_v[dst + lane]      = p[2 * DIMC + lane];
    g_v[dst + lane + 32] = p[2 * DIMC + lane + 32];
}

// ---------------- flash attention: 128 q-rows per block, 64 keys per iter ---
// Separate K / P / V smem regions: 3 barriers per key-tile iteration.
#define QSTR 132
#define KSTR 68
#define PSTR 132
#define NKIT (SEQ / 64)
// Qs + Ks + Ps + Vs
#define FLASH_SMEM ((64 * QSTR + 64 * KSTR + 64 * PSTR + 64 * 64) * 4)

__global__ __launch_bounds__(256, 2)
void flash_attn(float* __restrict__ ao0, float* __restrict__ ao1)
{
    extern __shared__ float sm[];
    float* Qs = sm;                  // [d=64][QSTR] (m-contiguous)
    float* Ks = Qs + 64 * QSTR;      // [d=64][KSTR] (n-contiguous)
    float* Ps = Ks + 64 * KSTR;      // [c=64][PSTR] (m-contiguous)
    float* Vs = Ps + 64 * PSTR;      // [c=64][64]   (d-contiguous)

    const int tid = threadIdx.x;
    const int tx = tid & 15, ty = tid >> 4;
    const int bh = blockIdx.y;
    const int sq0 = blockIdx.x * 128;
    const float* qg = g_q + (size_t)bh * SEQ * HD;
    const float* kg = g_k + (size_t)bh * SEQ * HD;
    const float* vg = g_v + (size_t)bh * SEQ * HD;

    // stage Q (transposed to d-major); Q already carries the 0.125 scale
#pragma unroll
    for (int it = 0; it < 8; it++) {
        int idx = tid + it * 256;
        int r = idx >> 4, dg = (idx & 15) << 2;
        float4 v = *(const float4*)&qg[(size_t)(sq0 + r) * HD + dg];
        Qs[(dg + 0) * QSTR + r] = v.x;
        Qs[(dg + 1) * QSTR + r] = v.y;
        Qs[(dg + 2) * QSTR + r] = v.z;
        Qs[(dg + 3) * QSTR + r] = v.w;
    }

    float mi[8], li[8], acc[8][4];
#pragma unroll
    for (int i = 0; i < 8; i++) {
        mi[i] = -1e30f; li[i] = 0.f;
#pragma unroll
        for (int j = 0; j < 4; j++) acc[i][j] = 0.f;
    }

    for (int kt = 0; kt < NKIT; kt++) {
        const int n0 = kt * 64;
        __syncthreads();   // prior iteration done reading Ks/Vs (and Qs staged, kt=0)
#pragma unroll
        for (int it = 0; it < 4; it++) {
            int idx = tid + it * 256;
            int n = idx >> 4, dg = (idx & 15) << 2;
            float4 kv = *(const float4*)&kg[(size_t)(n0 + n) * HD + dg];
            Ks[(dg + 0) * KSTR + n] = kv.x;
            Ks[(dg + 1) * KSTR + n] = kv.y;
            Ks[(dg + 2) * KSTR + n] = kv.z;
            Ks[(dg + 3) * KSTR + n] = kv.w;
            float4 vv = *(const float4*)&vg[(size_t)(n0 + n) * HD + dg];
            *(float4*)&Vs[n * 64 + dg] = vv;
        }
        __syncthreads();

        // S = Q K^T  (rows: 4ty+i and 64+4ty+i ; cols: 4tx+j)
        float s[8][4];
#pragma unroll
        for (int i = 0; i < 8; i++)
#pragma unroll
            for (int j = 0; j < 4; j++) s[i][j] = 0.f;

#pragma unroll 8
        for (int dk = 0; dk < 64; dk++) {
            float4 a0 = *(const float4*)&Qs[dk * QSTR + 4 * ty];
            float4 a1 = *(const float4*)&Qs[dk * QSTR + 64 + 4 * ty];
            float4 bb = *(const float4*)&Ks[dk * KSTR + 4 * tx];
            float ar[8] = {a0.x, a0.y, a0.z, a0.w, a1.x, a1.y, a1.z, a1.w};
            float br[4] = {bb.x, bb.y, bb.z, bb.w};
#pragma unroll
            for (int i = 0; i < 8; i++)
#pragma unroll
                for (int j = 0; j < 4; j++)
                    s[i][j] += ar[i] * br[j];
        }

        // online softmax (row groups of 16 lanes share a q-row)
#pragma unroll
        for (int i = 0; i < 8; i++) {
            float rm = fmaxf(fmaxf(s[i][0], s[i][1]), fmaxf(s[i][2], s[i][3]));
            rm = fmaxf(rm, __shfl_xor_sync(0xffffffffu, rm, 1));
            rm = fmaxf(rm, __shfl_xor_sync(0xffffffffu, rm, 2));
            rm = fmaxf(rm, __shfl_xor_sync(0xffffffffu, rm, 4));
            rm = fmaxf(rm, __shfl_xor_sync(0xffffffffu, rm, 8));
            float mnew = fmaxf(mi[i], rm);
            float corr = __expf(mi[i] - mnew);
            float rs = 0.f;
#pragma unroll
            for (int j = 0; j < 4; j++) {
                s[i][j] = __expf(s[i][j] - mnew);
                rs += s[i][j];
            }
            rs += __shfl_xor_sync(0xffffffffu, rs, 1);
            rs += __shfl_xor_sync(0xffffffffu, rs, 2);
            rs += __shfl_xor_sync(0xffffffffu, rs, 4);
            rs += __shfl_xor_sync(0xffffffffu, rs, 8);
            li[i] = li[i] * corr + rs;
            mi[i] = mnew;
#pragma unroll
            for (int j = 0; j < 4; j++) acc[i][j] *= corr;
        }

        // store P transposed: Ps[c][r] (own region — no barrier needed before)
#pragma unroll
        for (int i = 0; i < 8; i++) {
            int r = (i < 4) ? (4 * ty + i) : (64 + 4 * ty + i - 4);
#pragma unroll
            for (int j = 0; j < 4; j++)
                Ps[(4 * tx + j) * PSTR + r] = s[i][j];
        }
        __syncthreads();

        // O += P V
#pragma unroll 8
        for (int c = 0; c < 64; c++) {
            float4 a0 = *(const float4*)&Ps[c * PSTR + 4 * ty];
            float4 a1 = *(const float4*)&Ps[c * PSTR + 64 + 4 * ty];
            float4 bb = *(const float4*)&Vs[c * 64 + 4 * tx];
            float ar[8] = {a0.x, a0.y, a0.z, a0.w, a1.x, a1.y, a1.z, a1.w};
            float br[4] = {bb.x, bb.y, bb.z, bb.w};
#pragma unroll
            for (int i = 0; i < 8; i++)
#pragma unroll
                for (int j = 0; j < 4; j++)
                    acc[i][j] += ar[i] * br[j];
        }
    }

    // epilogue: out[b, n, h*64+d] per stream, normalized by li
    const int b_ = bh / HEADS, h = bh % HEADS;
#pragma unroll
    for (int i = 0; i < 8; i++) {
        int r = (i < 4) ? (4 * ty + i) : (64 + 4 * ty + i - 4);
        int sq = sq0 + r;
        int strm = sq >> 10;
        int tok = b_ * 1024 + (sq & 1023);
        float inv = 1.f / li[i];
        float4 o;
        o.x = acc[i][0] * inv; o.y = acc[i][1] * inv;
        o.z = acc[i][2] * inv; o.w = acc[i][3] * inv;
        float* dst = (strm ? ao1 : ao0) + (size_t)tok * DIMC + h * HD + 4 * tx;
        *(float4*)dst = o;
    }
}

// ---------------- launch --------------------------------------------------
extern "C" void kernel_launch(void* const* d_in, const int* in_sizes, int n_in,
                              void* d_out, int out_size)
{
    (void)in_sizes; (void)n_in; (void)out_size;
    const float* x       = (const float*)d_in[0];
    const float* y       = (const float*)d_in[1];
    const float* Wqkv_x  = (const float*)d_in[2];
    const float* bqkv_x  = (const float*)d_in[3];
    const float* Wqkv_y  = (const float*)d_in[4];
    const float* bqkv_y  = (const float*)d_in[5];
    const float* Wproj_x = (const float*)d_in[6];
    const float* bproj_x = (const float*)d_in[7];
    const float* Wproj_y = (const float*)d_in[8];
    const float* bproj_y = (const float*)d_in[9];
    const float* gq_x = (const float*)d_in[10];
    const float* bq_x = (const float*)d_in[11];
    const float* gk_x = (const float*)d_in[12];
    const float* bk_x = (const float*)d_in[13];
    const float* gq_y = (const float*)d_in[14];
    const float* bq_y = (const float*)d_in[15];
    const float* gk_y = (const float*)d_in[16];
    const float* bk_y = (const float*)d_in[17];
    float* out = (float*)d_out;

    float *qkv0, *qkv1, *ao0, *ao1;
    cudaGetSymbolAddress((void**)&qkv0, g_qkv0);
    cudaGetSymbolAddress((void**)&qkv1, g_qkv1);
    cudaGetSymbolAddress((void**)&ao0, g_ao0);
    cudaGetSymbolAddress((void**)&ao1, g_ao1);

    cudaFuncSetAttribute(flash_attn,
                         cudaFuncAttributeMaxDynamicSharedMemorySize, FLASH_SMEM);

    // 1) QKV projections
    dim3 g1(QKVN / 128, NTOK / 128);
    sgemm_nt_bias<<<g1, 256>>>(x, Wqkv_x, bqkv_x, qkv0, NTOK, QKVN, DIMC);
    sgemm_nt_bias<<<g1, 256>>>(y, Wqkv_y, bqkv_y, qkv1, NTOK, QKVN, DIMC);

    // 2) per-head LN on q,k + rearrange to [bh, seq, hd] (v copied)
    ln_split<<<NTOK * HEADS, 32>>>(qkv0, gq_x, bq_x, gk_x, bk_x, 0);
    ln_split<<<NTOK * HEADS, 32>>>(qkv1, gq_y, bq_y, gk_y, bk_y, 1);

    // 3) joint attention over seq=2048, flash-style
    flash_attn<<<dim3(SEQ / 128, NBH), 256, FLASH_SMEM>>>(ao0, ao1);

    // 4) output projections (ox -> first half of out, oy -> second half)
    dim3 g2(DIMC / 128, NTOK / 128);
    sgemm_nt_bias<<<g2, 256>>>(ao0, Wproj_x, bproj_x, out, NTOK, DIMC, DIMC);
    sgemm_nt_bias<<<g2, 256>>>(ao1, Wproj_y, bproj_y, out + (size_t)NTOK * DIMC,
                               NTOK, DIMC, DIMC);
}

// round 9
// speedup vs baseline: 2.4414x; 2.4414x over previous
#include <cuda_runtime.h>
#include <math.h>
#include <stdint.h>

// Problem constants
#define DIMC 768
#define NTOK 4096      // 4 batches * 1024 tokens per stream
#define QKVN 2304      // 3*DIM
#define HEADS 12
#define NBH 48         // 4*12
#define SEQ 2048       // concat seq
#define HD 64

// ---------------- scratch (device globals; no allocations allowed) ----------
__device__ float g_qkv0[NTOK * QKVN];
__device__ float g_qkv1[NTOK * QKVN];
__device__ float g_q[NBH * SEQ * HD];
__device__ float g_k[NBH * SEQ * HD];
__device__ float g_v[NBH * SEQ * HD];
__device__ float g_ao0[NTOK * DIMC];
__device__ float g_ao1[NTOK * DIMC];

__device__ __forceinline__ uint32_t f2tf32(float f) {
    uint32_t u;
    asm("cvt.rna.tf32.f32 %0, %1;" : "=r"(u) : "f"(f));
    return u;
}

__device__ __forceinline__ void mma_tf32(float c[4], const uint32_t a[4],
                                         const uint32_t b[2]) {
    asm volatile(
        "mma.sync.aligned.m16n8k8.row.col.f32.tf32.tf32.f32 "
        "{%0,%1,%2,%3}, {%4,%5,%6,%7}, {%8,%9}, {%0,%1,%2,%3};"
        : "+f"(c[0]), "+f"(c[1]), "+f"(c[2]), "+f"(c[3])
        : "r"(a[0]), "r"(a[1]), "r"(a[2]), "r"(a[3]), "r"(b[0]), "r"(b[1]));
}

// ---------------- tf32 GEMM: C[M,N] = A[M,K] @ B[N,K]^T + bias[N] -----------
// 128x128 tile, BK=16, 256 threads (8 warps, 2x4 warp grid, 64x32 per warp),
// double-buffered smem, tf32 conversion at staging time.
// blockIdx.z in {0,1} selects the (A,B,bias,C) set -> x/y streams fused into
// one launch to halve wave-quantization tails.
#define GPAD 136

__global__ __launch_bounds__(256, 2)
void sgemm_tf32_nt_bias2(const float* __restrict__ A0, const float* __restrict__ B0,
                         const float* __restrict__ bias0, float* __restrict__ C0,
                         const float* __restrict__ A1, const float* __restrict__ B1,
                         const float* __restrict__ bias1, float* __restrict__ C1,
                         int M, int N, int K)
{
    __shared__ uint32_t As[2][16][GPAD];
    __shared__ uint32_t Bs[2][16][GPAD];

    const int z = blockIdx.z;
    const float* A    = z ? A1 : A0;
    const float* B    = z ? B1 : B0;
    const float* bias = z ? bias1 : bias0;
    float*       C    = z ? C1 : C0;

    const int tid = threadIdx.x;
    const int bm = blockIdx.y * 128;
    const int bn = blockIdx.x * 128;
    const int lr = tid >> 1;            // staging row 0..127
    const int lk = (tid & 1) << 2;      // staging k offset 0 or 4
    const float* Ap = A + (size_t)(bm + lr) * K + lk;
    const float* Bp = B + (size_t)(bn + lr) * K + lk;

    const int lane = tid & 31;
    const int wid = tid >> 5;
    const int gr = lane >> 2;           // 0..7
    const int tg = lane & 3;            // 0..3
    const int m_base = (wid & 1) * 64;
    const int n_base = (wid >> 1) * 32;

    float acc[4][4][4];
#pragma unroll
    for (int mt = 0; mt < 4; mt++)
#pragma unroll
        for (int nt = 0; nt < 4; nt++)
#pragma unroll
            for (int i = 0; i < 4; i++) acc[mt][nt][i] = 0.f;

    // prologue: stage slab 0 (k=0..15)
    {
        float4 a0v = *(const float4*)(Ap + 0);
        float4 a1v = *(const float4*)(Ap + 8);
        float4 b0v = *(const float4*)(Bp + 0);
        float4 b1v = *(const float4*)(Bp + 8);
        As[0][lk + 0][lr] = f2tf32(a0v.x); As[0][lk + 1][lr] = f2tf32(a0v.y);
        As[0][lk + 2][lr] = f2tf32(a0v.z); As[0][lk + 3][lr] = f2tf32(a0v.w);
        As[0][lk + 8][lr] = f2tf32(a1v.x); As[0][lk + 9][lr] = f2tf32(a1v.y);
        As[0][lk +10][lr] = f2tf32(a1v.z); As[0][lk +11][lr] = f2tf32(a1v.w);
        Bs[0][lk + 0][lr] = f2tf32(b0v.x); Bs[0][lk + 1][lr] = f2tf32(b0v.y);
        Bs[0][lk + 2][lr] = f2tf32(b0v.z); Bs[0][lk + 3][lr] = f2tf32(b0v.w);
        Bs[0][lk + 8][lr] = f2tf32(b1v.x); Bs[0][lk + 9][lr] = f2tf32(b1v.y);
        Bs[0][lk +10][lr] = f2tf32(b1v.z); Bs[0][lk +11][lr] = f2tf32(b1v.w);
    }
    __syncthreads();

    int buf = 0;
    for (int k0 = 0; k0 < K; k0 += 16) {
        const bool more = (k0 + 16 < K);
        float4 a0v, a1v, b0v, b1v;
        if (more) {
            a0v = *(const float4*)(Ap + k0 + 16);
            a1v = *(const float4*)(Ap + k0 + 24);
            b0v = *(const float4*)(Bp + k0 + 16);
            b1v = *(const float4*)(Bp + k0 + 24);
        }

#pragma unroll
        for (int ks = 0; ks < 2; ks++) {
            const int kb = ks * 8;
            uint32_t bf[4][2];
#pragma unroll
            for (int nt = 0; nt < 4; nt++) {
                int col = n_base + nt * 8 + gr;
                bf[nt][0] = Bs[buf][kb + tg][col];
                bf[nt][1] = Bs[buf][kb + tg + 4][col];
            }
            uint32_t af[4][4];
#pragma unroll
            for (int mt = 0; mt < 4; mt++) {
                int row = m_base + mt * 16 + gr;
                af[mt][0] = As[buf][kb + tg][row];
                af[mt][1] = As[buf][kb + tg][row + 8];
                af[mt][2] = As[buf][kb + tg + 4][row];
                af[mt][3] = As[buf][kb + tg + 4][row + 8];
            }
#pragma unroll
            for (int mt = 0; mt < 4; mt++)
#pragma unroll
                for (int nt = 0; nt < 4; nt++)
                    mma_tf32(acc[mt][nt], af[mt], bf[nt]);
        }

        if (more) {
            int nb = buf ^ 1;
            As[nb][lk + 0][lr] = f2tf32(a0v.x); As[nb][lk + 1][lr] = f2tf32(a0v.y);
            As[nb][lk + 2][lr] = f2tf32(a0v.z); As[nb][lk + 3][lr] = f2tf32(a0v.w);
            As[nb][lk + 8][lr] = f2tf32(a1v.x); As[nb][lk + 9][lr] = f2tf32(a1v.y);
            As[nb][lk +10][lr] = f2tf32(a1v.z); As[nb][lk +11][lr] = f2tf32(a1v.w);
            Bs[nb][lk + 0][lr] = f2tf32(b0v.x); Bs[nb][lk + 1][lr] = f2tf32(b0v.y);
            Bs[nb][lk + 2][lr] = f2tf32(b0v.z); Bs[nb][lk + 3][lr] = f2tf32(b0v.w);
            Bs[nb][lk + 8][lr] = f2tf32(b1v.x); Bs[nb][lk + 9][lr] = f2tf32(b1v.y);
            Bs[nb][lk +10][lr] = f2tf32(b1v.z); Bs[nb][lk +11][lr] = f2tf32(b1v.w);
            __syncthreads();
            buf = nb;
        }
    }

    // epilogue: c0=(gr,2tg) c1=(gr,2tg+1) c2=(gr+8,2tg) c3=(gr+8,2tg+1)
#pragma unroll
    for (int mt = 0; mt < 4; mt++) {
        int r0 = bm + m_base + mt * 16 + gr;
#pragma unroll
        for (int nt = 0; nt < 4; nt++) {
            int c = bn + n_base + nt * 8 + 2 * tg;
            float bx0 = bias[c], bx1 = bias[c + 1];
            float2 o0 = {acc[mt][nt][0] + bx0, acc[mt][nt][1] + bx1};
            float2 o1 = {acc[mt][nt][2] + bx0, acc[mt][nt][3] + bx1};
            *(float2*)&C[(size_t)r0 * N + c] = o0;
            *(float2*)&C[(size_t)(r0 + 8) * N + c] = o1;
        }
    }
}

// ---------------- LayerNorm(q,k per head) + split/rearrange -----------------
__device__ __forceinline__ float warp_sum32(float v) {
#pragma unroll
    for (int o = 16; o > 0; o >>= 1) v += __shfl_xor_sync(0xffffffffu, v, o);
    return v;
}

// 8 warps per block, one warp per (token, head) row; blockIdx.y = stream.
__global__ __launch_bounds__(256)
void ln_split2(const float* __restrict__ qkvA, const float* __restrict__ qkvB,
               const float* __restrict__ gqA, const float* __restrict__ bqA,
               const float* __restrict__ gkA, const float* __restrict__ bkA,
               const float* __restrict__ gqB, const float* __restrict__ bqB,
               const float* __restrict__ gkB, const float* __restrict__ bkB)
{
    const int strm = blockIdx.y;
    const float* qkv = strm ? qkvB : qkvA;
    const float* gq = strm ? gqB : gqA;
    const float* bq = strm ? bqB : bqA;
    const float* gk = strm ? gkB : gkA;
    const float* bk = strm ? bkB : bkA;

    const int row = blockIdx.x * 8 + (threadIdx.x >> 5);  // 0..NTOK*HEADS-1
    const int t = row / HEADS, h = row % HEADS;
    const int lane = threadIdx.x & 31;
    const float* p = qkv + (size_t)t * QKVN + h * HD;
    const int b = t >> 10, n = t & 1023;
    const size_t dst = ((size_t)(b * HEADS + h) * SEQ + strm * 1024 + n) * HD;

    // q with LN (+0.125 scale folded in)
    float q0 = p[lane], q1 = p[lane + 32];
    float mu = warp_sum32(q0 + q1) * (1.f / 64.f);
    float var = warp_sum32(q0 * q0 + q1 * q1) * (1.f / 64.f) - mu * mu;
    float inv = rsqrtf(var + 1e-5f);
    g_q[dst + lane]      = ((q0 - mu) * inv * gq[lane]      + bq[lane])      * 0.125f;
    g_q[dst + lane + 32] = ((q1 - mu) * inv * gq[lane + 32] + bq[lane + 32]) * 0.125f;

    // k with LN
    float k0 = p[DIMC + lane], k1 = p[DIMC + lane + 32];
    mu = warp_sum32(k0 + k1) * (1.f / 64.f);
    var = warp_sum32(k0 * k0 + k1 * k1) * (1.f / 64.f) - mu * mu;
    inv = rsqrtf(var + 1e-5f);
    g_k[dst + lane]      = (k0 - mu) * inv * gk[lane]      + bk[lane];
    g_k[dst + lane + 32] = (k1 - mu) * inv * gk[lane + 32] + bk[lane + 32];

    // v copy
    g_v[dst + lane]      = p[2 * DIMC + lane];
    g_v[dst + lane + 32] = p[2 * DIMC + lane + 32];
}

// ---------------- tensor-core flash attention -------------------------------
// BM=128 q rows / CTA, BN=64 keys per iter, 8 warps; warp w owns q rows
// [16w, 16w+16). All operands natural [row][d] layout in smem (tf32 bits).
// mma m16n8k8 row.col; softmax rows never cross a warp.
#define QP 68
#define KP 68
#define VP 72
#define PP 68
#define NKIT (SEQ / 64)
#define FLASH_SMEM ((128 * QP + 64 * KP + 64 * VP + 128 * PP) * 4)

__global__ __launch_bounds__(256, 2)
void flash_attn_tc(float* __restrict__ ao0, float* __restrict__ ao1)
{
    extern __shared__ uint32_t smu[];
    uint32_t* Qs = smu;              // [128][QP] tf32
    uint32_t* Ks = Qs + 128 * QP;    // [64][KP]  tf32
    uint32_t* Vs = Ks + 64 * KP;     // [64][VP]  tf32
    uint32_t* Ps = Vs + 64 * VP;     // [128][PP] tf32

    const int tid = threadIdx.x;
    const int lane = tid & 31;
    const int w = tid >> 5;
    const int gr = lane >> 2;        // 0..7
    const int tg = lane & 3;         // 0..3
    const int mb = w * 16;           // warp's q-row base within tile
    const int bh = blockIdx.y;
    const int sq0 = blockIdx.x * 128;
    const float* qg = g_q + (size_t)bh * SEQ * HD;
    const float* kg = g_k + (size_t)bh * SEQ * HD;
    const float* vg = g_v + (size_t)bh * SEQ * HD;

    // stage Q (natural layout, tf32): 128 rows x 64 d
#pragma unroll
    for (int it = 0; it < 8; it++) {
        int idx = tid + it * 256;
        int r = idx >> 4, dg = (idx & 15) << 2;
        float4 v = *(const float4*)&qg[(size_t)(sq0 + r) * HD + dg];
        uint4 u = {f2tf32(v.x), f2tf32(v.y), f2tf32(v.z), f2tf32(v.w)};
        *(uint4*)&Qs[r * QP + dg] = u;
    }

    float mi0 = -1e30f, mi1 = -1e30f, li0 = 0.f, li1 = 0.f;
    float o[8][4];
#pragma unroll
    for (int nt = 0; nt < 8; nt++)
#pragma unroll
        for (int i = 0; i < 4; i++) o[nt][i] = 0.f;

    for (int kt = 0; kt < NKIT; kt++) {
        const int n0 = kt * 64;
        __syncthreads();   // prior iter done reading Ks/Vs (kt=0: Q staged)
#pragma unroll
        for (int it = 0; it < 4; it++) {
            int idx = tid + it * 256;
            int n = idx >> 4, dg = (idx & 15) << 2;
            float4 kv = *(const float4*)&kg[(size_t)(n0 + n) * HD + dg];
            uint4 ku = {f2tf32(kv.x), f2tf32(kv.y), f2tf32(kv.z), f2tf32(kv.w)};
            *(uint4*)&Ks[n * KP + dg] = ku;
            float4 vv = *(const float4*)&vg[(size_t)(n0 + n) * HD + dg];
            uint4 vu = {f2tf32(vv.x), f2tf32(vv.y), f2tf32(vv.z), f2tf32(vv.w)};
            *(uint4*)&Vs[n * VP + dg] = vu;
        }
        __syncthreads();

        // S[16][64] = Q K^T via mma. A=Q rows mb..mb+15; B element (k=d,n)=K[n][d].
        float s[8][4];
#pragma unroll
        for (int nt = 0; nt < 8; nt++)
#pragma unroll
            for (int i = 0; i < 4; i++) s[nt][i] = 0.f;

#pragma unroll
        for (int d0 = 0; d0 < 64; d0 += 8) {
            uint32_t af[4];
            af[0] = Qs[(mb + gr) * QP + d0 + tg];
            af[1] = Qs[(mb + gr + 8) * QP + d0 + tg];
            af[2] = Qs[(mb + gr) * QP + d0 + tg + 4];
            af[3] = Qs[(mb + gr + 8) * QP + d0 + tg + 4];
#pragma unroll
            for (int nt = 0; nt < 8; nt++) {
                uint32_t bf[2];
                bf[0] = Ks[(nt * 8 + gr) * KP + d0 + tg];
                bf[1] = Ks[(nt * 8 + gr) * KP + d0 + tg + 4];
                mma_tf32(s[nt], af, bf);
            }
        }

        // online softmax. Thread holds: row0=mb+gr cols (nt*8+2tg, +1) in s[nt][0..1],
        // row1=mb+gr+8 in s[nt][2..3]. Row spans lanes gr*4+{0..3} -> shfl 1,2.
        float rm0 = -1e30f, rm1 = -1e30f;
#pragma unroll
        for (int nt = 0; nt < 8; nt++) {
            rm0 = fmaxf(rm0, fmaxf(s[nt][0], s[nt][1]));
            rm1 = fmaxf(rm1, fmaxf(s[nt][2], s[nt][3]));
        }
        rm0 = fmaxf(rm0, __shfl_xor_sync(0xffffffffu, rm0, 1));
        rm0 = fmaxf(rm0, __shfl_xor_sync(0xffffffffu, rm0, 2));
        rm1 = fmaxf(rm1, __shfl_xor_sync(0xffffffffu, rm1, 1));
        rm1 = fmaxf(rm1, __shfl_xor_sync(0xffffffffu, rm1, 2));

        float mn0 = fmaxf(mi0, rm0), mn1 = fmaxf(mi1, rm1);
        float cr0 = __expf(mi0 - mn0), cr1 = __expf(mi1 - mn1);
        float rs0 = 0.f, rs1 = 0.f;
#pragma unroll
        for (int nt = 0; nt < 8; nt++) {
            s[nt][0] = __expf(s[nt][0] - mn0);
            s[nt][1] = __expf(s[nt][1] - mn0);
            s[nt][2] = __expf(s[nt][2] - mn1);
            s[nt][3] = __expf(s[nt][3] - mn1);
            rs0 += s[nt][0] + s[nt][1];
            rs1 += s[nt][2] + s[nt][3];
        }
        rs0 += __shfl_xor_sync(0xffffffffu, rs0, 1);
        rs0 += __shfl_xor_sync(0xffffffffu, rs0, 2);
        rs1 += __shfl_xor_sync(0xffffffffu, rs1, 1);
        rs1 += __shfl_xor_sync(0xffffffffu, rs1, 2);
        li0 = li0 * cr0 + rs0; mi0 = mn0;
        li1 = li1 * cr1 + rs1; mi1 = mn1;
#pragma unroll
        for (int nt = 0; nt < 8; nt++) {
            o[nt][0] *= cr0; o[nt][1] *= cr0;
            o[nt][2] *= cr1; o[nt][3] *= cr1;
        }

        // store P (tf32) to own warp's rows; only this warp reads it back
#pragma unroll
        for (int nt = 0; nt < 8; nt++) {
            Ps[(mb + gr) * PP + nt * 8 + 2 * tg]     = f2tf32(s[nt][0]);
            Ps[(mb + gr) * PP + nt * 8 + 2 * tg + 1] = f2tf32(s[nt][1]);
            Ps[(mb + gr + 8) * PP + nt * 8 + 2 * tg]     = f2tf32(s[nt][2]);
            Ps[(mb + gr + 8) * PP + nt * 8 + 2 * tg + 1] = f2tf32(s[nt][3]);
        }
        __syncwarp();

        // O[16][64] += P[16][64] V[64][64]. A=P (k=c), B element (k=c,n=d)=V[c][d].
#pragma unroll
        for (int c0 = 0; c0 < 64; c0 += 8) {
            uint32_t pf[4];
            pf[0] = Ps[(mb + gr) * PP + c0 + tg];
            pf[1] = Ps[(mb + gr + 8) * PP + c0 + tg];
            pf[2] = Ps[(mb + gr) * PP + c0 + tg + 4];
            pf[3] = Ps[(mb + gr + 8) * PP + c0 + tg + 4];
#pragma unroll
            for (int nt = 0; nt < 8; nt++) {
                uint32_t vf[2];
                vf[0] = Vs[(c0 + tg) * VP + nt * 8 + gr];
                vf[1] = Vs[(c0 + tg + 4) * VP + nt * 8 + gr];
                mma_tf32(o[nt], pf, vf);
            }
        }
    }

    // epilogue: rows sq0+mb+gr, +8; cols h*64 + nt*8 + 2tg
    const int b_ = bh / HEADS, h = bh % HEADS;
    const float inv0 = 1.f / li0, inv1 = 1.f / li1;
    const int r0 = sq0 + mb + gr, r1 = r0 + 8;
    float* dst0 = ((r0 >> 10) ? ao1 : ao0) +
                  (size_t)(b_ * 1024 + (r0 & 1023)) * DIMC + h * HD + 2 * tg;
    float* dst1 = ((r1 >> 10) ? ao1 : ao0) +
                  (size_t)(b_ * 1024 + (r1 & 1023)) * DIMC + h * HD + 2 * tg;
#pragma unroll
    for (int nt = 0; nt < 8; nt++) {
        float2 p0 = {o[nt][0] * inv0, o[nt][1] * inv0};
        float2 p1 = {o[nt][2] * inv1, o[nt][3] * inv1};
        *(float2*)(dst0 + nt * 8) = p0;
        *(float2*)(dst1 + nt * 8) = p1;
    }
}

// ---------------- launch --------------------------------------------------
extern "C" void kernel_launch(void* const* d_in, const int* in_sizes, int n_in,
                              void* d_out, int out_size)
{
    (void)in_sizes; (void)n_in; (void)out_size;
    const float* x       = (const float*)d_in[0];
    const float* y       = (const float*)d_in[1];
    const float* Wqkv_x  = (const float*)d_in[2];
    const float* bqkv_x  = (const float*)d_in[3];
    const float* Wqkv_y  = (const float*)d_in[4];
    const float* bqkv_y  = (const float*)d_in[5];
    const float* Wproj_x = (const float*)d_in[6];
    const float* bproj_x = (const float*)d_in[7];
    const float* Wproj_y = (const float*)d_in[8];
    const float* bproj_y = (const float*)d_in[9];
    const float* gq_x = (const float*)d_in[10];
    const float* bq_x = (const float*)d_in[11];
    const float* gk_x = (const float*)d_in[12];
    const float* bk_x = (const float*)d_in[13];
    const float* gq_y = (const float*)d_in[14];
    const float* bq_y = (const float*)d_in[15];
    const float* gk_y = (const float*)d_in[16];
    const float* bk_y = (const float*)d_in[17];
    float* out = (float*)d_out;

    float *qkv0, *qkv1, *ao0, *ao1;
    cudaGetSymbolAddress((void**)&qkv0, g_qkv0);
    cudaGetSymbolAddress((void**)&qkv1, g_qkv1);
    cudaGetSymbolAddress((void**)&ao0, g_ao0);
    cudaGetSymbolAddress((void**)&ao1, g_ao1);

    cudaFuncSetAttribute(flash_attn_tc,
                         cudaFuncAttributeMaxDynamicSharedMemorySize, FLASH_SMEM);

    // 1) QKV projections, x+y fused via blockIdx.z (tf32 tensor core)
    dim3 g1(QKVN / 128, NTOK / 128, 2);
    sgemm_tf32_nt_bias2<<<g1, 256>>>(x, Wqkv_x, bqkv_x, qkv0,
                                     y, Wqkv_y, bqkv_y, qkv1,
                                     NTOK, QKVN, DIMC);

    // 2) per-head LN on q,k + rearrange to [bh, seq, hd], both streams fused
    ln_split2<<<dim3(NTOK * HEADS / 8, 2), 256>>>(
        qkv0, qkv1,
        gq_x, bq_x, gk_x, bk_x,
        gq_y, bq_y, gk_y, bk_y);

    // 3) joint attention over seq=2048 (tf32 tensor core flash)
    flash_attn_tc<<<dim3(SEQ / 128, NBH), 256, FLASH_SMEM>>>(ao0, ao1);

    // 4) output projections, x+y fused via blockIdx.z (tf32 tensor core)
    dim3 g2(DIMC / 128, NTOK / 128, 2);
    sgemm_tf32_nt_bias2<<<g2, 256>>>(ao0, Wproj_x, bproj_x, out,
                                     ao1, Wproj_y, bproj_y, out + (size_t)NTOK * DIMC,
                                     NTOK, DIMC, DIMC);
}